// round 1
// baseline (speedup 1.0000x reference)
#include <cuda_runtime.h>

// RNN scan: out[t] = tanh(input_proj[t] + h_{t-1} @ W^T + bias), h_{-1} = hidden.
// Baseline: fused fp32 SIMT GEMM per step, 512 graph-captured launches.
// h state is chained through the output buffer itself (out[t-1] == h_{t-1}),
// so no scratch memory is needed (allocation-free, graph-capturable).

#define TM 32
#define TN 32
#define KT 32
#define PAD 1
#define HDIM 1024

__global__ __launch_bounds__(128) void rnn_step_kernel(
    const float* __restrict__ x_t,    // (B,H) slice of input_proj
    const float* __restrict__ hprev,  // (B,H)
    const float* __restrict__ W,      // (H,H) row-major, we need h @ W^T
    const float* __restrict__ bias,   // (H)
    float* __restrict__ hout)         // (B,H)
{
    __shared__ float As[KT][TM + PAD]; // As[k][m]
    __shared__ float Ws[KT][TN + PAD]; // Ws[k][n]

    const int tid = threadIdx.x;       // 0..127
    const int tm  = tid >> 3;          // 0..15  (m stride 16)
    const int tn  = tid & 7;           // 0..7   (n stride 8)
    const int m0  = blockIdx.y * TM;
    const int n0  = blockIdx.x * TN;

    float acc[2][4];
#pragma unroll
    for (int i = 0; i < 2; i++)
#pragma unroll
        for (int j = 0; j < 4; j++) acc[i][j] = 0.0f;

    for (int kt = 0; kt < HDIM; kt += KT) {
        // Load 32x32 A tile (hprev) and 32x32 W tile, transposed into [k][*].
        // 1024 elems each / 128 threads = 8 per thread, fully coalesced on
        // the k-contiguous global layout; padded smem makes the transposed
        // store conflict-free (stride 33).
#pragma unroll
        for (int p = 0; p < 8; p++) {
            int idx = p * 128 + tid;
            int r = idx >> 5;       // row within tile (m or n)
            int c = idx & 31;       // k within tile
            As[c][r] = hprev[(size_t)(m0 + r) * HDIM + kt + c];
            Ws[c][r] = W[(size_t)(n0 + r) * HDIM + kt + c];
        }
        __syncthreads();

#pragma unroll
        for (int k = 0; k < KT; k++) {
            float a0 = As[k][tm];
            float a1 = As[k][tm + 16];
            float b0 = Ws[k][tn];
            float b1 = Ws[k][tn + 8];
            float b2 = Ws[k][tn + 16];
            float b3 = Ws[k][tn + 24];
            acc[0][0] += a0 * b0; acc[0][1] += a0 * b1;
            acc[0][2] += a0 * b2; acc[0][3] += a0 * b3;
            acc[1][0] += a1 * b0; acc[1][1] += a1 * b1;
            acc[1][2] += a1 * b2; acc[1][3] += a1 * b3;
        }
        __syncthreads();
    }

#pragma unroll
    for (int i = 0; i < 2; i++) {
        int m = m0 + tm + i * 16;
#pragma unroll
        for (int j = 0; j < 4; j++) {
            int n = n0 + tn + j * 8;
            float v = x_t[(size_t)m * HDIM + n] + acc[i][j] + bias[n];
            hout[(size_t)m * HDIM + n] = tanhf(v);
        }
    }
}

extern "C" void kernel_launch(void* const* d_in, const int* in_sizes, int n_in,
                              void* d_out, int out_size)
{
    // metadata order: input_proj (S,B,H) f32, hidden (B,H) f32,
    //                 weight_hh (H,H) f32, bias_hh (H) f32
    const float* input_proj = (const float*)d_in[0];
    const float* hidden     = (const float*)d_in[1];
    const float* W          = (const float*)d_in[2];
    const float* bias       = (const float*)d_in[3];
    float* out = (float*)d_out;

    const int S = 512, B = 128;
    const size_t step = (size_t)B * HDIM;

    dim3 grid(HDIM / TN, B / TM); // (32, 4) = 128 CTAs
    dim3 block(128);

    for (int t = 0; t < S; t++) {
        const float* hprev = (t == 0) ? hidden : (out + (size_t)(t - 1) * step);
        rnn_step_kernel<<<grid, block>>>(input_proj + (size_t)t * step,
                                         hprev, W, bias,
                                         out + (size_t)t * step);
    }
}

// round 3
// speedup vs baseline: 3.3061x; 3.3061x over previous
#include <cuda_runtime.h>

// Persistent-kernel RNN scan, single launch:
//   out[t] = tanh(input_proj[t] + h_{t-1} @ W^T + bias),  h_{-1} = hidden
// Grid = 128 CTAs arranged 4(M) x 32(N); each CTA owns a 32x32 output tile
// and keeps its 32-column W slice (128KB) in SMEM for all 512 steps.
// Per step: cp.async double-buffered h tiles, packed f32x2 FMA, counting
// grid barrier between steps. h state chains through the output buffer.

#define S      512
#define BM     128
#define HDIM   1024
#define NCTA   128
#define TM     32          // rows per CTA
#define TN     32          // cols per CTA
#define TK     128         // k-tile
#define NTILE  (HDIM / TK) // 8
#define HPAD   132         // smem h row stride (floats), conflict-free

__device__ unsigned g_slots[S];   // zero-initialized at load

// ---- packed f32x2 helpers ----
__device__ __forceinline__ void fma2(unsigned long long& acc,
                                     unsigned long long a,
                                     unsigned long long b) {
    asm("fma.rn.f32x2 %0, %1, %2, %3;" : "=l"(acc) : "l"(a), "l"(b), "l"(acc));
}
__device__ __forceinline__ unsigned long long splat2(float v) {
    unsigned long long r;
    unsigned u = __float_as_uint(v);
    asm("mov.b64 %0, {%1, %1};" : "=l"(r) : "r"(u));
    return r;
}
__device__ __forceinline__ void unpack2(unsigned long long p, float& lo, float& hi) {
    asm("mov.b64 {%0, %1}, %2;" : "=f"(lo), "=f"(hi) : "l"(p));
}
__device__ __forceinline__ unsigned long long d2l(double d) {
    return (unsigned long long)__double_as_longlong(d);
}

// ---- cp.async helpers ----
__device__ __forceinline__ void cp16(unsigned dst, const void* src) {
    asm volatile("cp.async.cg.shared.global [%0], [%1], 16;" :: "r"(dst), "l"(src));
}
__device__ __forceinline__ void cp_commit() { asm volatile("cp.async.commit_group;"); }
__device__ __forceinline__ void cp_wait1()  { asm volatile("cp.async.wait_group 1;"); }
__device__ __forceinline__ void cp_wait0()  { asm volatile("cp.async.wait_group 0;"); }

__global__ __launch_bounds__(128, 1) void rnn_persistent(
    const float* __restrict__ X,     // (S, BM, HDIM)
    const float* __restrict__ H0,    // (BM, HDIM)
    const float* __restrict__ W,     // (HDIM, HDIM), row n holds W[n][:]
    const float* __restrict__ bias,  // (HDIM)
    float* __restrict__ out)         // (S, BM, HDIM)
{
    extern __shared__ __align__(16) float smem[];
    float* Wt  = smem;                  // [HDIM][TN]: Wt[k*32 + col] = W[n0+col][k]
    float* hsA = smem + HDIM * TN;      // [TM][HPAD]
    float* hsB = hsA + TM * HPAD;

    const int tid = threadIdx.x;        // 0..127
    const int bid = blockIdx.x;         // 0..127
    const int mi  = bid >> 5;           // 0..3
    const int ni  = bid & 31;           // 0..31
    const int m0  = mi * TM;
    const int n0  = ni * TN;
    const int tn  = tid & 7;            // 0..7  -> cols tn*4..tn*4+3
    const int tm  = tid >> 3;           // 0..15 -> rows tm, tm+16

    // cross-launch cleanup of the one leftover barrier slot (see barrier note)
    if (bid == 0 && tid == 0) g_slots[S - 2] = 0;

    // ---- one-time: W slice, transposed into SMEM (k-major rows of 32) ----
    for (int idx = tid; idx < TN * (HDIM / 4); idx += 128) {
        int col = idx >> 8;             // 0..31
        int kq  = idx & 255;            // float4 index along k
        float4 w = ((const float4*)(W + (size_t)(n0 + col) * HDIM))[kq];
        Wt[(kq * 4 + 0) * TN + col] = w.x;
        Wt[(kq * 4 + 1) * TN + col] = w.y;
        Wt[(kq * 4 + 2) * TN + col] = w.z;
        Wt[(kq * 4 + 3) * TN + col] = w.w;
    }
    const float4 bv = *(const float4*)(bias + n0 + tn * 4);
    __syncthreads();

    const unsigned hsAu = (unsigned)__cvta_generic_to_shared(hsA);
    const unsigned hsBu = (unsigned)__cvta_generic_to_shared(hsB);
    const int gr0 = m0 + tm;        // global rows this thread outputs
    const int gr1 = m0 + tm + 16;
    const int gc  = n0 + tn * 4;    // global first col

    for (int t = 0; t < S; t++) {
        const float* hsrc = t ? (out + (size_t)(t - 1) * BM * HDIM) : H0;

        // x prefetch (independent of h)
        const float* xb = X + (size_t)t * BM * HDIM;
        float4 xv0 = *(const float4*)(xb + (size_t)gr0 * HDIM + gc);
        float4 xv1 = *(const float4*)(xb + (size_t)gr1 * HDIM + gc);

        unsigned long long acc00 = 0ull, acc01 = 0ull, acc10 = 0ull, acc11 = 0ull;

        // issue tile 0
#pragma unroll
        for (int i = 0; i < 8; i++) {
            int idx = i * 128 + tid;
            int r = idx >> 5, q = idx & 31;
            cp16(hsAu + (unsigned)((r * HPAD + q * 4) * 4),
                 hsrc + (size_t)(m0 + r) * HDIM + q * 4);
        }
        cp_commit();

        for (int p = 0; p < NTILE; p++) {
            if (p < NTILE - 1) {
                const float* base = hsrc + (p + 1) * TK;
                unsigned dstb = ((p + 1) & 1) ? hsBu : hsAu;
#pragma unroll
                for (int i = 0; i < 8; i++) {
                    int idx = i * 128 + tid;
                    int r = idx >> 5, q = idx & 31;
                    cp16(dstb + (unsigned)((r * HPAD + q * 4) * 4),
                         base + (size_t)(m0 + r) * HDIM + q * 4);
                }
                cp_commit();
                cp_wait1();
            } else {
                cp_wait0();
            }
            __syncthreads();

            const float* hb = (p & 1) ? hsB : hsA;
            const float* wp = Wt + (size_t)p * TK * TN;
#pragma unroll 4
            for (int kq = 0; kq < TK / 4; kq++) {
                float4 a0 = *(const float4*)(hb + tm * HPAD + kq * 4);
                float4 a1 = *(const float4*)(hb + (tm + 16) * HPAD + kq * 4);
                const float* a0p = &a0.x;
                const float* a1p = &a1.x;
#pragma unroll
                for (int u = 0; u < 4; u++) {
                    double2 wd = ((const double2*)(wp + (kq * 4 + u) * TN))[tn];
                    unsigned long long w01 = d2l(wd.x);
                    unsigned long long w23 = d2l(wd.y);
                    unsigned long long h0 = splat2(a0p[u]);
                    unsigned long long h1 = splat2(a1p[u]);
                    fma2(acc00, h0, w01); fma2(acc01, h0, w23);
                    fma2(acc10, h1, w01); fma2(acc11, h1, w23);
                }
            }
            __syncthreads();
        }

        // epilogue: + x + bias, tanh, store
        {
            float c0, c1, c2, c3;
            float4 o;
            unpack2(acc00, c0, c1); unpack2(acc01, c2, c3);
            o.x = tanhf(c0 + xv0.x + bv.x);
            o.y = tanhf(c1 + xv0.y + bv.y);
            o.z = tanhf(c2 + xv0.z + bv.z);
            o.w = tanhf(c3 + xv0.w + bv.w);
            *(float4*)(out + (size_t)t * BM * HDIM + (size_t)gr0 * HDIM + gc) = o;
            unpack2(acc10, c0, c1); unpack2(acc11, c2, c3);
            o.x = tanhf(c0 + xv1.x + bv.x);
            o.y = tanhf(c1 + xv1.y + bv.y);
            o.z = tanhf(c2 + xv1.z + bv.z);
            o.w = tanhf(c3 + xv1.w + bv.w);
            *(float4*)(out + (size_t)t * BM * HDIM + (size_t)gr1 * HDIM + gc) = o;
        }

        // grid barrier between steps (counting slots; lag-1 reset)
        if (t < S - 1) {
            __syncthreads();
            if (tid == 0) {
                __threadfence();
                atomicAdd(&g_slots[t], 1u);
                while (*(volatile unsigned*)&g_slots[t] < NCTA) { }
                __threadfence();
                if (bid == 0 && t > 0) g_slots[t - 1] = 0; // all CTAs are past t-1
            }
            __syncthreads();
        }
    }
}

extern "C" void kernel_launch(void* const* d_in, const int* in_sizes, int n_in,
                              void* d_out, int out_size)
{
    const float* input_proj = (const float*)d_in[0];
    const float* hidden     = (const float*)d_in[1];
    const float* W          = (const float*)d_in[2];
    const float* bias       = (const float*)d_in[3];
    float* out = (float*)d_out;

    const int smem_bytes = (HDIM * TN + 2 * TM * HPAD) * (int)sizeof(float); // ~161KB
    cudaFuncSetAttribute(rnn_persistent,
                         cudaFuncAttributeMaxDynamicSharedMemorySize, smem_bytes);

    rnn_persistent<<<NCTA, 128, smem_bytes>>>(input_proj, hidden, W, bias, out);
}